// round 3
// baseline (speedup 1.0000x reference)
#include <cuda_runtime.h>

#define BB 4
#define HH 480
#define WW 640
#define HWp (HH * WW)
#define NPIX (BB * HWp)

// Scratch (static __device__ arrays — no allocation)
__device__ float g_aff[9 * NPIX];   // normalized affinities, plane layout [(b*9+k)*HW + p]
__device__ float g_ping[NPIX];      // g = f * conf, ping-pong
__device__ float g_pong[NPIX];

// ---------------------------------------------------------------------------
// Pass A: affinity normalization (tanh once!) + initial g = feat*conf
// ---------------------------------------------------------------------------
__global__ void __launch_bounds__(256)
precompute_kernel(const float* __restrict__ feat_init,
                  const float* __restrict__ guidance,
                  const float* __restrict__ confidence,
                  const float* __restrict__ feat_fix,
                  const float* __restrict__ aff_scale) {
    int idx = blockIdx.x * blockDim.x + threadIdx.x;
    if (idx >= NPIX) return;
    int b = idx / HWp;
    int p = idx - b * HWp;

    const float* gp = guidance + ((size_t)b * 24 + 16) * HWp + p;
    float scale = aff_scale[0] + 1e-8f;

    float a[8];
    float s = 1e-4f;
#pragma unroll
    for (int j = 0; j < 8; j++) {
        a[j] = tanhf(gp[(size_t)j * HWp]) / scale;
        s += fabsf(a[j]);
    }
    s = fmaxf(s, 1.0f);
    float inv = 1.0f / s;
    float sum = 0.0f;
#pragma unroll
    for (int j = 0; j < 8; j++) { a[j] *= inv; sum += a[j]; }
    float aref = 1.0f - sum;

    float* ap = g_aff + (size_t)b * 9 * HWp + p;
#pragma unroll
    for (int j = 0; j < 4; j++) ap[(size_t)j * HWp] = a[j];
    ap[(size_t)4 * HWp] = aref;
#pragma unroll
    for (int j = 4; j < 8; j++) ap[(size_t)(j + 1) * HWp] = a[j];

    // initial g = feat * conf
    float ff = feat_fix[idx];
    float fi = feat_init[idx];
    float cf = confidence[idx];
    bool m = ff > 0.0f;
    float conf = m ? 1.0f : cf;
    float feat = m ? ff : fi;
    g_ping[idx] = feat * conf;
}

// ---------------------------------------------------------------------------
// Propagation step: g_out = A * sum_k aff_k * bilinear(g_in, pos_k) + feat_fix
// last==1: write f instead of g (A -> (1-m))
// ---------------------------------------------------------------------------
__global__ void __launch_bounds__(256)
prop_kernel(const float* __restrict__ guidance,
            const float* __restrict__ confidence,
            const float* __restrict__ feat_fix,
            const float* __restrict__ gin,
            float* __restrict__ gout,
            int last) {
    int idx = blockIdx.x * blockDim.x + threadIdx.x;
    if (idx >= NPIX) return;
    int b = idx / HWp;
    int p = idx - b * HWp;
    int y = p / WW;
    int x = p - y * WW;

    const float* offp = guidance + (size_t)b * 24 * HWp + p;
    const float* affp = g_aff + (size_t)b * 9 * HWp + p;
    const float* img  = gin + (size_t)b * HWp;

    const int kyv[9] = {-1, -1, -1, 0, 0, 0, 1, 1, 1};
    const int kxv[9] = {-1, 0, 1, -1, 0, 1, -1, 0, 1};

    float acc = 0.0f;
#pragma unroll
    for (int k = 0; k < 9; k++) {
        float dy, dx;
        if (k == 4) {
            dy = 0.0f; dx = 0.0f;
        } else {
            int k2 = (k < 4) ? k : (k - 1);
            dy = offp[(size_t)(2 * k2) * HWp];
            dx = offp[(size_t)(2 * k2 + 1) * HWp];
        }
        float py = (float)(y + kyv[k]) + dy;
        float px = (float)(x + kxv[k]) + dx;
        float y0f = floorf(py);
        float x0f = floorf(px);
        int y0 = (int)y0f;
        int x0 = (int)x0f;
        float wy = py - y0f;
        float wx = px - x0f;

        float w00 = (1.0f - wy) * (1.0f - wx);
        float w01 = (1.0f - wy) * wx;
        float w10 = wy * (1.0f - wx);
        float w11 = wy * wx;

        bool vy0 = (unsigned)y0 < (unsigned)HH;
        bool vy1 = (unsigned)(y0 + 1) < (unsigned)HH;
        bool vx0 = (unsigned)x0 < (unsigned)WW;
        bool vx1 = (unsigned)(x0 + 1) < (unsigned)WW;

        w00 = (vy0 && vx0) ? w00 : 0.0f;
        w01 = (vy0 && vx1) ? w01 : 0.0f;
        w10 = (vy1 && vx0) ? w10 : 0.0f;
        w11 = (vy1 && vx1) ? w11 : 0.0f;

        int cy0 = min(max(y0, 0), HH - 1);
        int cy1 = min(max(y0 + 1, 0), HH - 1);
        int cx0 = min(max(x0, 0), WW - 1);
        int cx1 = min(max(x0 + 1, 0), WW - 1);

        const float* r0 = img + (size_t)cy0 * WW;
        const float* r1 = img + (size_t)cy1 * WW;
        float v00 = r0[cx0];
        float v01 = r0[cx1];
        float v10 = r1[cx0];
        float v11 = r1[cx1];

        float samp = w00 * v00;
        samp = fmaf(w01, v01, samp);
        samp = fmaf(w10, v10, samp);
        samp = fmaf(w11, v11, samp);

        acc = fmaf(affp[(size_t)k * HWp], samp, acc);
    }

    float ff = feat_fix[idx];
    float notm = (ff > 0.0f) ? 0.0f : 1.0f;
    float wA = last ? notm : notm * confidence[idx];
    gout[idx] = fmaf(wA, acc, ff);
}

// ---------------------------------------------------------------------------
extern "C" void kernel_launch(void* const* d_in, const int* in_sizes, int n_in,
                              void* d_out, int out_size) {
    const float* feat_init  = (const float*)d_in[0];
    const float* guidance   = (const float*)d_in[1];
    const float* confidence = (const float*)d_in[2];
    const float* feat_fix   = (const float*)d_in[3];
    const float* aff_scale  = (const float*)d_in[4];
    float* out = (float*)d_out;

    float* ping = nullptr;
    float* pong = nullptr;
    cudaGetSymbolAddress((void**)&ping, g_ping);
    cudaGetSymbolAddress((void**)&pong, g_pong);

    const int threads = 256;
    const int blocks = (NPIX + threads - 1) / threads;

    precompute_kernel<<<blocks, threads>>>(feat_init, guidance, confidence,
                                           feat_fix, aff_scale);

    // 17 intermediate propagation steps (g-space), ping-pong
    float* cur = ping;
    float* nxt = pong;
    for (int i = 1; i <= 17; i++) {
        prop_kernel<<<blocks, threads>>>(guidance, confidence, feat_fix,
                                         cur, nxt, /*last=*/0);
        float* t = cur; cur = nxt; nxt = t;
    }
    // final step writes f directly to d_out
    prop_kernel<<<blocks, threads>>>(guidance, confidence, feat_fix,
                                     cur, out, /*last=*/1);
}

// round 7
// speedup vs baseline: 1.1144x; 1.1144x over previous
#include <cuda_runtime.h>

#define BB 4
#define HH 480
#define WW 640
#define HWp (HH * WW)
#define NPIX (BB * HWp)

// Scratch (static __device__ arrays — no allocation)
__device__ float  g_aff[9 * NPIX];    // normalized affinities, plane layout [(b*9+k)*HW + p]
__device__ float2 g_off[8 * NPIX];    // packed (dy,dx) per tap, plane layout [(b*8+t)*HW + p]
__device__ float  g_wA [NPIX];        // (1-m)*confidence
__device__ float  g_ping[NPIX];       // g = f * conf, ping-pong
__device__ float  g_pong[NPIX];

// ---------------------------------------------------------------------------
// Pass A: affinity normalization (tanh once) + offset packing + wA + initial g
// ---------------------------------------------------------------------------
__global__ void __launch_bounds__(256)
precompute_kernel(const float* __restrict__ feat_init,
                  const float* __restrict__ guidance,
                  const float* __restrict__ confidence,
                  const float* __restrict__ feat_fix,
                  const float* __restrict__ aff_scale) {
    int idx = blockIdx.x * blockDim.x + threadIdx.x;
    if (idx >= NPIX) return;
    int b = idx / HWp;
    int p = idx - b * HWp;

    const float* gbase = guidance + (size_t)b * 24 * HWp + p;

    // pack offsets: tap t <-> guidance channels (2t, 2t+1)
#pragma unroll
    for (int t = 0; t < 8; t++) {
        float dy = gbase[(size_t)(2 * t) * HWp];
        float dx = gbase[(size_t)(2 * t + 1) * HWp];
        g_off[(size_t)(b * 8 + t) * HWp + p] = make_float2(dy, dx);
    }

    // affinity normalization
    const float* gp = gbase + (size_t)16 * HWp;
    float scale = aff_scale[0] + 1e-8f;
    float a[8];
    float s = 1e-4f;
#pragma unroll
    for (int j = 0; j < 8; j++) {
        a[j] = tanhf(gp[(size_t)j * HWp]) / scale;
        s += fabsf(a[j]);
    }
    s = fmaxf(s, 1.0f);
    float inv = 1.0f / s;
    float sum = 0.0f;
#pragma unroll
    for (int j = 0; j < 8; j++) { a[j] *= inv; sum += a[j]; }
    float aref = 1.0f - sum;

    float* ap = g_aff + (size_t)b * 9 * HWp + p;
#pragma unroll
    for (int j = 0; j < 4; j++) ap[(size_t)j * HWp] = a[j];
    ap[(size_t)4 * HWp] = aref;
#pragma unroll
    for (int j = 4; j < 8; j++) ap[(size_t)(j + 1) * HWp] = a[j];

    // wA = (1-m)*conf ; initial g = feat * conf
    float ff = feat_fix[idx];
    float fi = feat_init[idx];
    float cf = confidence[idx];
    bool m = ff > 0.0f;
    float conf = m ? 1.0f : cf;
    float feat = m ? ff : fi;
    g_wA[idx]  = m ? 0.0f : cf;
    g_ping[idx] = feat * conf;
}

// ---------------------------------------------------------------------------
// Bilinear sample with zero-outside semantics (clamped gather + masked weights)
// ---------------------------------------------------------------------------
__device__ __forceinline__ float bil(const float* __restrict__ img,
                                     float py, float px) {
    float y0f = floorf(py);
    float x0f = floorf(px);
    int y0 = (int)y0f;
    int x0 = (int)x0f;
    float wy = py - y0f;
    float wx = px - x0f;

    float w00 = (1.0f - wy) * (1.0f - wx);
    float w01 = (1.0f - wy) * wx;
    float w10 = wy * (1.0f - wx);
    float w11 = wy * wx;

    bool vy0 = (unsigned)y0 < (unsigned)HH;
    bool vy1 = (unsigned)(y0 + 1) < (unsigned)HH;
    bool vx0 = (unsigned)x0 < (unsigned)WW;
    bool vx1 = (unsigned)(x0 + 1) < (unsigned)WW;

    w00 = (vy0 && vx0) ? w00 : 0.0f;
    w01 = (vy0 && vx1) ? w01 : 0.0f;
    w10 = (vy1 && vx0) ? w10 : 0.0f;
    w11 = (vy1 && vx1) ? w11 : 0.0f;

    int cy0 = min(max(y0, 0), HH - 1);
    int cy1 = min(max(y0 + 1, 0), HH - 1);
    int cx0 = min(max(x0, 0), WW - 1);
    int cx1 = min(max(x0 + 1, 0), WW - 1);

    const float* r0 = img + (size_t)cy0 * WW;
    const float* r1 = img + (size_t)cy1 * WW;
    float samp = w00 * r0[cx0];
    samp = fmaf(w01, r0[cx1], samp);
    samp = fmaf(w10, r1[cx0], samp);
    samp = fmaf(w11, r1[cx1], samp);
    return samp;
}

// ---------------------------------------------------------------------------
// Propagation step, 2 pixels per thread:
//   g_out = wA * (sum_t aff_t * bilinear(g_in, pos_t) + aff_c * g_in[p]) + ff
// last==1: wA replaced by (1-m) derived from ff
// ---------------------------------------------------------------------------
__global__ void __launch_bounds__(256)
prop_kernel(const float* __restrict__ feat_fix,
            const float* __restrict__ gin,
            float* __restrict__ gout,
            int last) {
    int pair = blockIdx.x * blockDim.x + threadIdx.x;
    int base = pair * 2;
    if (base >= NPIX) return;
    int b = base / HWp;
    int p = base - b * HWp;         // even, both pixels in same batch
    int y0r = p / WW;
    int x0r = p - y0r * WW;
    // pixel 1 coords (may wrap to next row)
    int x1r = x0r + 1;
    int y1r = y0r;
    if (x1r == WW) { x1r = 0; y1r++; }

    const float2* offp = g_off + (size_t)b * 8 * HWp + p;   // float2 per pixel
    const float*  affp = g_aff + (size_t)b * 9 * HWp + p;
    const float*  img  = gin + (size_t)b * HWp;

    const int kyv[8] = {-1, -1, -1, 0, 0, 1, 1, 1};
    const int kxv[8] = {-1, 0, 1, -1, 1, -1, 0, 1};

    float acc0 = 0.0f, acc1 = 0.0f;

#pragma unroll
    for (int t = 0; t < 8; t++) {
        // one float4 = (dy0,dx0,dy1,dx1) for the two pixels
        float4 o = *reinterpret_cast<const float4*>(offp + (size_t)t * HWp);
        int j = (t < 4) ? t : (t + 1);   // affinity plane index
        float2 a = *reinterpret_cast<const float2*>(affp + (size_t)j * HWp);

        float s0 = bil(img, (float)(y0r + kyv[t]) + o.x,
                            (float)(x0r + kxv[t]) + o.y);
        float s1 = bil(img, (float)(y1r + kyv[t]) + o.z,
                            (float)(x1r + kxv[t]) + o.w);
        acc0 = fmaf(a.x, s0, acc0);
        acc1 = fmaf(a.y, s1, acc1);
    }

    // center tap: offset is exactly zero -> sample = g[p]
    {
        float2 ac = *reinterpret_cast<const float2*>(affp + (size_t)4 * HWp);
        float2 gc = *reinterpret_cast<const float2*>(img + p);
        acc0 = fmaf(ac.x, gc.x, acc0);
        acc1 = fmaf(ac.y, gc.y, acc1);
    }

    float2 ffv = *reinterpret_cast<const float2*>(feat_fix + base);
    float2 w;
    if (last) {
        w.x = (ffv.x > 0.0f) ? 0.0f : 1.0f;
        w.y = (ffv.y > 0.0f) ? 0.0f : 1.0f;
    } else {
        w = *reinterpret_cast<const float2*>(g_wA + base);
    }

    float2 r;
    r.x = fmaf(w.x, acc0, ffv.x);
    r.y = fmaf(w.y, acc1, ffv.y);
    *reinterpret_cast<float2*>(gout + base) = r;
}

// ---------------------------------------------------------------------------
extern "C" void kernel_launch(void* const* d_in, const int* in_sizes, int n_in,
                              void* d_out, int out_size) {
    const float* feat_init  = (const float*)d_in[0];
    const float* guidance   = (const float*)d_in[1];
    const float* confidence = (const float*)d_in[2];
    const float* feat_fix   = (const float*)d_in[3];
    const float* aff_scale  = (const float*)d_in[4];
    float* out = (float*)d_out;

    float* ping = nullptr;
    float* pong = nullptr;
    cudaGetSymbolAddress((void**)&ping, g_ping);
    cudaGetSymbolAddress((void**)&pong, g_pong);

    const int threads = 256;
    const int blocksA = (NPIX + threads - 1) / threads;
    const int blocksP = (NPIX / 2 + threads - 1) / threads;

    precompute_kernel<<<blocksA, threads>>>(feat_init, guidance, confidence,
                                            feat_fix, aff_scale);

    float* cur = ping;
    float* nxt = pong;
    for (int i = 1; i <= 17; i++) {
        prop_kernel<<<blocksP, threads>>>(feat_fix, cur, nxt, /*last=*/0);
        float* t = cur; cur = nxt; nxt = t;
    }
    prop_kernel<<<blocksP, threads>>>(feat_fix, cur, out, /*last=*/1);
}

// round 9
// speedup vs baseline: 1.1933x; 1.0708x over previous
#include <cuda_runtime.h>

#define BB 4
#define HH 480
#define WW 640
#define HWp (HH * WW)
#define NPIX (BB * HWp)

// Scratch (static __device__ arrays — no allocation)
__device__ float  g_aff[9 * NPIX];    // normalized affinities, plane layout [(b*9+k)*HW + p]
__device__ float2 g_off[8 * NPIX];    // packed (dy,dx) per tap, plane layout [(b*8+t)*HW + p]
__device__ float  g_wA [NPIX];        // (1-m)*confidence
__device__ float  g_ping[NPIX];       // g = f * conf, ping-pong
__device__ float  g_pong[NPIX];

// ---------------------------------------------------------------------------
// Pass A: affinity normalization (tanh once) + offset packing + wA + initial g
// ---------------------------------------------------------------------------
__global__ void __launch_bounds__(256)
precompute_kernel(const float* __restrict__ feat_init,
                  const float* __restrict__ guidance,
                  const float* __restrict__ confidence,
                  const float* __restrict__ feat_fix,
                  const float* __restrict__ aff_scale) {
    int idx = blockIdx.x * blockDim.x + threadIdx.x;
    if (idx >= NPIX) return;
    int b = idx / HWp;
    int p = idx - b * HWp;

    const float* gbase = guidance + (size_t)b * 24 * HWp + p;

    // pack offsets: tap t <-> guidance channels (2t, 2t+1)
#pragma unroll
    for (int t = 0; t < 8; t++) {
        float dy = gbase[(size_t)(2 * t) * HWp];
        float dx = gbase[(size_t)(2 * t + 1) * HWp];
        g_off[(size_t)(b * 8 + t) * HWp + p] = make_float2(dy, dx);
    }

    // affinity normalization
    const float* gp = gbase + (size_t)16 * HWp;
    float scale = aff_scale[0] + 1e-8f;
    float a[8];
    float s = 1e-4f;
#pragma unroll
    for (int j = 0; j < 8; j++) {
        a[j] = tanhf(gp[(size_t)j * HWp]) / scale;
        s += fabsf(a[j]);
    }
    s = fmaxf(s, 1.0f);
    float inv = 1.0f / s;
    float sum = 0.0f;
#pragma unroll
    for (int j = 0; j < 8; j++) { a[j] *= inv; sum += a[j]; }
    float aref = 1.0f - sum;

    float* ap = g_aff + (size_t)b * 9 * HWp + p;
#pragma unroll
    for (int j = 0; j < 4; j++) ap[(size_t)j * HWp] = a[j];
    ap[(size_t)4 * HWp] = aref;
#pragma unroll
    for (int j = 4; j < 8; j++) ap[(size_t)(j + 1) * HWp] = a[j];

    // wA = (1-m)*conf ; initial g = feat * conf
    float ff = feat_fix[idx];
    float fi = feat_init[idx];
    float cf = confidence[idx];
    bool m = ff > 0.0f;
    float conf = m ? 1.0f : cf;
    float feat = m ? ff : fi;
    g_wA[idx]  = m ? 0.0f : cf;
    g_ping[idx] = feat * conf;
}

// ---------------------------------------------------------------------------
// Bilinear sample with zero-outside semantics (clamped gather + masked weights)
// ---------------------------------------------------------------------------
__device__ __forceinline__ float bil(const float* __restrict__ img,
                                     float py, float px) {
    float y0f = floorf(py);
    float x0f = floorf(px);
    int y0 = (int)y0f;
    int x0 = (int)x0f;
    float wy = py - y0f;
    float wx = px - x0f;

    float w00 = (1.0f - wy) * (1.0f - wx);
    float w01 = (1.0f - wy) * wx;
    float w10 = wy * (1.0f - wx);
    float w11 = wy * wx;

    bool vy0 = (unsigned)y0 < (unsigned)HH;
    bool vy1 = (unsigned)(y0 + 1) < (unsigned)HH;
    bool vx0 = (unsigned)x0 < (unsigned)WW;
    bool vx1 = (unsigned)(x0 + 1) < (unsigned)WW;

    w00 = (vy0 && vx0) ? w00 : 0.0f;
    w01 = (vy0 && vx1) ? w01 : 0.0f;
    w10 = (vy1 && vx0) ? w10 : 0.0f;
    w11 = (vy1 && vx1) ? w11 : 0.0f;

    int cy0 = min(max(y0, 0), HH - 1);
    int cy1 = min(max(y0 + 1, 0), HH - 1);
    int cx0 = min(max(x0, 0), WW - 1);
    int cx1 = min(max(x0 + 1, 0), WW - 1);

    const float* r0 = img + (size_t)cy0 * WW;
    const float* r1 = img + (size_t)cy1 * WW;
    float samp = w00 * r0[cx0];
    samp = fmaf(w01, r0[cx1], samp);
    samp = fmaf(w10, r1[cx0], samp);
    samp = fmaf(w11, r1[cx1], samp);
    return samp;
}

// ---------------------------------------------------------------------------
// Propagation step over a 2-batch group [b0, b0+2), 2 pixels per thread:
//   g_out = wA * (sum_t aff_t * bilinear(g_in, pos_t) + aff_c * g_in[p]) + ff
// last==1: wA replaced by (1-m) derived from ff
// ---------------------------------------------------------------------------
__global__ void __launch_bounds__(256)
prop_kernel(const float* __restrict__ feat_fix,
            const float* __restrict__ gin,
            float* __restrict__ gout,
            int last, int b0) {
    int pair = blockIdx.x * blockDim.x + threadIdx.x;
    int base2 = pair * 2;                    // index within the 2-batch group
    if (base2 >= 2 * HWp) return;
    int brel = base2 / HWp;
    int b = b0 + brel;
    int p = base2 - brel * HWp;              // even; both pixels same batch
    int gbase = b * HWp + p;                 // global flat index of pixel 0

    int y0r = p / WW;
    int x0r = p - y0r * WW;
    int x1r = x0r + 1;
    int y1r = y0r;
    if (x1r == WW) { x1r = 0; y1r++; }

    const float2* offp = g_off + (size_t)b * 8 * HWp + p;
    const float*  affp = g_aff + (size_t)b * 9 * HWp + p;
    const float*  img  = gin + (size_t)b * HWp;

    // Front-batch all offset loads (raises MLP; regs ~64 is intended)
    float4 o[8];
#pragma unroll
    for (int t = 0; t < 8; t++)
        o[t] = *reinterpret_cast<const float4*>(offp + (size_t)t * HWp);

    const int kyv[8] = {-1, -1, -1, 0, 0, 1, 1, 1};
    const int kxv[8] = {-1, 0, 1, -1, 1, -1, 0, 1};

    float acc0 = 0.0f, acc1 = 0.0f;

#pragma unroll
    for (int t = 0; t < 8; t++) {
        int j = (t < 4) ? t : (t + 1);   // affinity plane index
        float2 a = *reinterpret_cast<const float2*>(affp + (size_t)j * HWp);

        float s0 = bil(img, (float)(y0r + kyv[t]) + o[t].x,
                            (float)(x0r + kxv[t]) + o[t].y);
        float s1 = bil(img, (float)(y1r + kyv[t]) + o[t].z,
                            (float)(x1r + kxv[t]) + o[t].w);
        acc0 = fmaf(a.x, s0, acc0);
        acc1 = fmaf(a.y, s1, acc1);
    }

    // center tap: offset is exactly zero -> sample = g[p]
    {
        float2 ac = *reinterpret_cast<const float2*>(affp + (size_t)4 * HWp);
        float2 gc = *reinterpret_cast<const float2*>(img + p);
        acc0 = fmaf(ac.x, gc.x, acc0);
        acc1 = fmaf(ac.y, gc.y, acc1);
    }

    float2 ffv = *reinterpret_cast<const float2*>(feat_fix + gbase);
    float2 w;
    if (last) {
        w.x = (ffv.x > 0.0f) ? 0.0f : 1.0f;
        w.y = (ffv.y > 0.0f) ? 0.0f : 1.0f;
    } else {
        w = *reinterpret_cast<const float2*>(g_wA + gbase);
    }

    float2 r;
    r.x = fmaf(w.x, acc0, ffv.x);
    r.y = fmaf(w.y, acc1, ffv.y);
    *reinterpret_cast<float2*>(gout + gbase) = r;
}

// ---------------------------------------------------------------------------
extern "C" void kernel_launch(void* const* d_in, const int* in_sizes, int n_in,
                              void* d_out, int out_size) {
    const float* feat_init  = (const float*)d_in[0];
    const float* guidance   = (const float*)d_in[1];
    const float* confidence = (const float*)d_in[2];
    const float* feat_fix   = (const float*)d_in[3];
    const float* aff_scale  = (const float*)d_in[4];
    float* out = (float*)d_out;

    float* ping = nullptr;
    float* pong = nullptr;
    cudaGetSymbolAddress((void**)&ping, g_ping);
    cudaGetSymbolAddress((void**)&pong, g_pong);

    const int threads = 256;
    const int blocksA = (NPIX + threads - 1) / threads;
    const int blocksP = (2 * HWp / 2 + threads - 1) / threads;   // 1200

    precompute_kernel<<<blocksA, threads>>>(feat_init, guidance, confidence,
                                            feat_fix, aff_scale);

    // Process batch groups {0,1} then {2,3}: each group's invariant working
    // set (~52 MB) stays L2-resident across its 18 iterations.
    for (int b0 = 0; b0 < BB; b0 += 2) {
        float* cur = ping;
        float* nxt = pong;
        for (int i = 1; i <= 17; i++) {
            prop_kernel<<<blocksP, threads>>>(feat_fix, cur, nxt, /*last=*/0, b0);
            float* t = cur; cur = nxt; nxt = t;
        }
        prop_kernel<<<blocksP, threads>>>(feat_fix, cur, out, /*last=*/1, b0);
    }
}